// round 10
// baseline (speedup 1.0000x reference)
#include <cuda_runtime.h>
#include <math_constants.h>
#include <cstdint>

#define BB 8
#define NN 4096
#define DD 16
#define OO 64
#define KK 20
#define KP 24            // per-split fast-pass pad
#define SPLIT 8          // candidate splits per query
#define QTR (NN/SPLIT)   // 512 candidates per split
#define CNT (8LL*4096*20)

#define THR 64           // threads per knn block
#define QPB 128          // queries per knn block (2 per thread)
#define TC 256           // candidate tile rows
#define WARM 64          // candidates before first threshold compact
#define BUFCAP 352       // per-query pending buffer (local mem)

// ---------------- scratch (static device globals: no allocation) ------------
__device__ float  g_u[BB*NN*OO];
__device__ float  g_v[BB*NN*OO];
__device__ int    g_idx[BB*NN*KK];          // final knn indices
__device__ int    g_pidx[BB*NN*SPLIT*KP];   // per-split fast top-24 indices
__device__ float  g_sqf[BB*NN];             // XLA-emulated fp32 sum(x*x)
__device__ double g_sum[OO];
__device__ double g_sumsq[OO];
__device__ float  g_a[OO];
__device__ float  g_c[OO];

// ---------------- kernel 0: zero accumulators --------------------------------
__global__ void zero_sums() {
    int t = threadIdx.x;
    if (t < OO) { g_sum[t] = 0.0; g_sumsq[t] = 0.0; }
}

// ---------------- kernel 0b: XLA-emulated per-point squared norms -----------
// DO NOT CHANGE (bit-exact emulation of reference rounding; validated R3).
__global__ void sq_kernel(const float* __restrict__ x) {
    int p = blockIdx.x * blockDim.x + threadIdx.x;
    const float4* xp = (const float4*)(x + (size_t)p * DD);
    float s[4];
#pragma unroll
    for (int i = 0; i < 4; i++) {
        float4 v = xp[i];
        float a = __fmul_rn(v.x, v.x);
        a = __fadd_rn(a, __fmul_rn(v.y, v.y));
        a = __fadd_rn(a, __fmul_rn(v.z, v.z));
        a = __fadd_rn(a, __fmul_rn(v.w, v.w));
        s[i] = a;
    }
    g_sqf[p] = __fadd_rn(__fadd_rn(s[0], s[2]), __fadd_rn(s[1], s[3]));
}

// ---------------- kernel 1: per-point projections u, v ----------------------
__global__ void proj_kernel(const float* __restrict__ x,
                            const float* __restrict__ W) {
    __shared__ float Wt[2*DD][OO];
    __shared__ float xr[4][DD];
    int tid = threadIdx.x;
    for (int i = tid; i < OO*2*DD; i += blockDim.x) {
        int o = i / (2*DD), c = i % (2*DD);
        Wt[c][o] = W[i];
    }
    int p0 = blockIdx.x * 4;
    if (tid < 4*DD) xr[tid >> 4][tid & 15] = x[p0*DD + tid];
    __syncthreads();
    int o  = tid & 63;
    int nl = tid >> 6;
    float cacc = 0.f, facc = 0.f;
#pragma unroll
    for (int d = 0; d < DD; d++) {
        float xv = xr[nl][d];
        cacc = fmaf(Wt[d][o],      xv, cacc);
        facc = fmaf(Wt[DD + d][o], xv, facc);
    }
    int p = p0 + nl;
    g_u[p*OO + o] = cacc - facc;
    g_v[p*OO + o] = facc;
}

// ---------------- kNN helpers ------------------------------------------------
__device__ __forceinline__ float dot4(float4 a, float4 b) {
    return fmaf(a.x, b.x, fmaf(a.y, b.y, fmaf(a.z, b.z, a.w * b.w)));
}

__device__ __forceinline__ unsigned long long pack_key(float d, int gidx) {
    unsigned s = __float_as_uint(d);
    s ^= ((unsigned)((int)s >> 31)) | 0x80000000u;   // monotone f32->u32
    return ((unsigned long long)s << 32) | (unsigned)gidx;
}

__device__ __forceinline__ float unpack_d(unsigned long long key) {
    unsigned s = (unsigned)(key >> 32);
    s = (s & 0x80000000u) ? (s ^ 0x80000000u) : ~s;
    return __uint_as_float(s);
}

// drain pending buffer into thread-local sorted top-KP (rare path).
// buffer entries are u64 keys (monotone d, idx): insert by key < keeps
// exact (d asc, idx asc) order.
__device__ void compactk(unsigned long long* __restrict__ buf, int& cnt,
                         unsigned long long* __restrict__ hp, float& thr) {
    unsigned long long worst = hp[KP-1];
    for (int i = 0; i < cnt; i++) {
        unsigned long long key = buf[i];
        if (key < worst) {
            int j = KP - 1;
            while (j > 0 && key < hp[j-1]) { hp[j] = hp[j-1]; j--; }
            hp[j] = key;
            worst = hp[KP-1];
        }
    }
    cnt = 0;
    thr = unpack_d(worst);
}

// ---------------- kernel 2a: fast-pass kNN (R4-style scalar, SPLIT=8) -------
// 2 queries per thread; score d' = sq_c - 2*q.c = d2 - sq_q (rank-equivalent
// per query). grid = BB * (NN/QPB) * SPLIT = 2048 blocks of 64 threads.

#define KNN_BODY(MLO, MHI)                                                    \
    _Pragma("unroll 2")                                                       \
    for (int m = (MLO); m < (MHI); m++) {                                     \
        float4 c0 = xs[m*4+0], c1 = xs[m*4+1], c2 = xs[m*4+2], c3 = xs[m*4+3];\
        float s = sqs[m];                                                     \
        float pA0 = a0.x * c0.x;                                              \
        float pA1 = a1.x * c1.x;                                              \
        float pA2 = a2.x * c2.x;                                              \
        float pA3 = a3.x * c3.x;                                              \
        pA0 = fmaf(a0.y, c0.y, pA0); pA1 = fmaf(a1.y, c1.y, pA1);             \
        pA2 = fmaf(a2.y, c2.y, pA2); pA3 = fmaf(a3.y, c3.y, pA3);             \
        pA0 = fmaf(a0.z, c0.z, pA0); pA1 = fmaf(a1.z, c1.z, pA1);             \
        pA2 = fmaf(a2.z, c2.z, pA2); pA3 = fmaf(a3.z, c3.z, pA3);             \
        pA0 = fmaf(a0.w, c0.w, pA0); pA1 = fmaf(a1.w, c1.w, pA1);             \
        pA2 = fmaf(a2.w, c2.w, pA2); pA3 = fmaf(a3.w, c3.w, pA3);             \
        float dA = fmaf(-2.f, (pA0 + pA1) + (pA2 + pA3), s);                  \
        float pB0 = b0.x * c0.x;                                              \
        float pB1 = b1.x * c1.x;                                              \
        float pB2 = b2.x * c2.x;                                              \
        float pB3 = b3.x * c3.x;                                              \
        pB0 = fmaf(b0.y, c0.y, pB0); pB1 = fmaf(b1.y, c1.y, pB1);             \
        pB2 = fmaf(b2.y, c2.y, pB2); pB3 = fmaf(b3.y, c3.y, pB3);             \
        pB0 = fmaf(b0.z, c0.z, pB0); pB1 = fmaf(b1.z, c1.z, pB1);             \
        pB2 = fmaf(b2.z, c2.z, pB2); pB3 = fmaf(b3.z, c3.z, pB3);             \
        pB0 = fmaf(b0.w, c0.w, pB0); pB1 = fmaf(b1.w, c1.w, pB1);             \
        pB2 = fmaf(b2.w, c2.w, pB2); pB3 = fmaf(b3.w, c3.w, pB3);             \
        float dB = fmaf(-2.f, (pB0 + pB1) + (pB2 + pB3), s);                  \
        int gi = cbase + t0 + m;                                              \
        if (dA < thr0) buf0[cnt0++] = pack_key(dA, gi);                       \
        if (dB < thr1) buf1[cnt1++] = pack_key(dB, gi);                       \
    }

__global__ __launch_bounds__(THR, 12) void knn_part_kernel(const float* __restrict__ x) {
    __shared__ float4 xs[TC*4];     // 16KB
    __shared__ float  sqs[TC];      // 1KB

    int tid   = threadIdx.x;
    int split = blockIdx.x & (SPLIT-1);
    int qg    = (blockIdx.x >> 3) & 31;
    int b     = blockIdx.x >> 8;
    int qn0   = qg * QPB + tid;
    int qn1   = qn0 + THR;
    int cbase = split * QTR;

    const float* xb  = x + (size_t)b * NN * DD;
    const float* sqb = g_sqf + (size_t)b * NN;

    const float4* qpa = (const float4*)(xb + (size_t)qn0 * DD);
    const float4* qpb = (const float4*)(xb + (size_t)qn1 * DD);
    float4 a0 = qpa[0], a1 = qpa[1], a2 = qpa[2], a3 = qpa[3];
    float4 b0 = qpb[0], b1 = qpb[1], b2 = qpb[2], b3 = qpb[3];

    unsigned long long hp0[KP], hp1[KP];         // local mem (rare access)
#pragma unroll
    for (int j = 0; j < KP; j++) { hp0[j] = ~0ull; hp1[j] = ~0ull; }
    unsigned long long buf0[BUFCAP], buf1[BUFCAP];
    int cnt0 = 0, cnt1 = 0;
    float thr0 = CUDART_INF_F, thr1 = CUDART_INF_F;

    for (int t0 = 0; t0 < QTR; t0 += TC) {
        // stage tile
#pragma unroll
        for (int i = 0; i < TC/THR; i++) {
            int r = tid + i * THR;
            const float4* src = (const float4*)(xb + (size_t)(cbase + t0 + r) * DD);
            xs[r*4 + 0] = src[0]; xs[r*4 + 1] = src[1];
            xs[r*4 + 2] = src[2]; xs[r*4 + 3] = src[3];
            sqs[r] = sqb[cbase + t0 + r];
        }
        __syncthreads();

        if (t0 == 0) {
            KNN_BODY(0, WARM)
            compactk(buf0, cnt0, hp0, thr0);      // finite threshold early
            compactk(buf1, cnt1, hp1, thr1);
            KNN_BODY(WARM, TC)
        } else {
            KNN_BODY(0, TC)
        }
        __syncthreads();

        if (cnt0 >= BUFCAP - TC) compactk(buf0, cnt0, hp0, thr0);
        if (cnt1 >= BUFCAP - TC) compactk(buf1, cnt1, hp1, thr1);
    }
    compactk(buf0, cnt0, hp0, thr0);
    compactk(buf1, cnt1, hp1, thr1);

    int* o0 = g_pidx + (((size_t)b * NN + qn0) * SPLIT + split) * KP;
    int* o1 = g_pidx + (((size_t)b * NN + qn1) * SPLIT + split) * KP;
#pragma unroll
    for (int j = 0; j < KP; j++) {
        o0[j] = (int)(hp0[j] & 0xFFFFFFFFu);
        o1[j] = (int)(hp1[j] & 0xFFFFFFFFu);
    }
}

// ---------------- kernel 2b: merge splits + emulated-reference refinement ---
// FROZEN numerics (validated R3): serial-FFMA dot k ascending;
// d2 = fl( fl(sqn + sqc) - fl(2*dot) ); u64 key = (monotone d2, idx).
#define TQM 64
__global__ __launch_bounds__(TQM) void knn_merge_kernel(const float* __restrict__ x) {
    int tid = threadIdx.x;
    int b   = blockIdx.x >> 6;
    int qn  = ((blockIdx.x & 63) << 6) + tid;
    const float* xb  = x + (size_t)b * NN * DD;
    const float* sqb = g_sqf + (size_t)b * NN;

    const float4* qp = (const float4*)(xb + (size_t)qn * DD);
    float4 q0 = qp[0], q1 = qp[1], q2 = qp[2], q3 = qp[3];
    float sqn = sqb[qn];

    unsigned long long outk[KK];
#pragma unroll
    for (int j = 0; j < KK; j++) outk[j] = 0xFFFFFFFFFFFFFFFFull;

    const int* pin = g_pidx + ((size_t)b * NN + qn) * SPLIT * KP;
#pragma unroll 4
    for (int j = 0; j < SPLIT * KP; j++) {
        int ci = pin[j];
        const float4* cp = (const float4*)(xb + (size_t)ci * DD);
        float4 c0 = cp[0], c1 = cp[1], c2 = cp[2], c3 = cp[3];
        float acc = 0.f;
        acc = fmaf(q0.x, c0.x, acc); acc = fmaf(q0.y, c0.y, acc);
        acc = fmaf(q0.z, c0.z, acc); acc = fmaf(q0.w, c0.w, acc);
        acc = fmaf(q1.x, c1.x, acc); acc = fmaf(q1.y, c1.y, acc);
        acc = fmaf(q1.z, c1.z, acc); acc = fmaf(q1.w, c1.w, acc);
        acc = fmaf(q2.x, c2.x, acc); acc = fmaf(q2.y, c2.y, acc);
        acc = fmaf(q2.z, c2.z, acc); acc = fmaf(q2.w, c2.w, acc);
        acc = fmaf(q3.x, c3.x, acc); acc = fmaf(q3.y, c3.y, acc);
        acc = fmaf(q3.z, c3.z, acc); acc = fmaf(q3.w, c3.w, acc);
        float ssum = __fadd_rn(sqn, sqb[ci]);
        float d2   = __fsub_rn(ssum, __fmul_rn(2.0f, acc));
        unsigned long long key = pack_key(d2, ci);
        if (key < outk[KK-1]) {
            outk[KK-1] = key;
#pragma unroll
            for (int t = KK-1; t > 0; --t) {
                if (outk[t] < outk[t-1]) {
                    unsigned long long tmp = outk[t];
                    outk[t] = outk[t-1]; outk[t-1] = tmp;
                } else break;
            }
        }
    }

    int* outp = g_idx + ((size_t)b * NN + qn) * KK;
#pragma unroll
    for (int j = 0; j < KK; j++) outp[j] = (int)(outk[j] & 0xFFFFFFFFu);
}

// ---------------- kernel 3: per-channel sum / sumsq over (b,n,k) ------------
__global__ void sums_kernel() {
    int tid = threadIdx.x;
    int o = tid & 63;
    int g = tid >> 6;
    float s = 0.f, s2 = 0.f;
    int r0 = (blockIdx.x * 4 + g) * 32;
    for (int i = 0; i < 32; i++) {
        int r = r0 + i;
        int b = r >> 12;
        float u = g_u[(size_t)r * OO + o];
        const int* ip = g_idx + (size_t)r * KK;
#pragma unroll
        for (int k = 0; k < KK; k++) {
            int gi = ip[k];
            float h = u + g_v[(((size_t)b << 12) + gi) * OO + o];
            s += h;
            s2 = fmaf(h, h, s2);
        }
    }
    atomicAdd(&g_sum[o],   (double)s);
    atomicAdd(&g_sumsq[o], (double)s2);
}

// ---------------- kernel 4: finalize affine coefficients --------------------
__global__ void finalize_kernel(const float* __restrict__ gamma,
                                const float* __restrict__ beta) {
    int o = threadIdx.x;
    if (o < OO) {
        double mean = g_sum[o] / (double)CNT;
        double var  = g_sumsq[o] / (double)CNT - mean * mean;
        double rstd = 1.0 / sqrt(var + 1e-5);
        float a = gamma[o] * (float)rstd;
        g_a[o] = a;
        g_c[o] = fmaf(-(float)mean, a, beta[o]);
    }
}

// ---------------- kernel 5: write output (coalesced, smem-staged) -----------
__global__ void out_kernel(float* __restrict__ out) {
    __shared__ float su[NN];
    __shared__ float sv[NN];
    int b = blockIdx.x >> 6;
    int o = blockIdx.x & 63;
    float a = g_a[o], c = g_c[o];
    int tid = threadIdx.x;
    size_t base = (size_t)b * NN * OO;
    for (int i = tid; i < NN; i += blockDim.x) {
        su[i] = fmaf(a, g_u[base + (size_t)i * OO + o], c);
        sv[i] = a * g_v[base + (size_t)i * OO + o];
    }
    __syncthreads();
    const int* ip = g_idx + (size_t)b * NN * KK;
    float* op = out + (size_t)blockIdx.x * (NN * KK);
    for (int e = tid; e < NN * KK; e += blockDim.x) {
        int n = e / KK;
        int gi = ip[e];
        float y = su[n] + sv[gi];
        op[e] = fmaxf(y, 0.f);
    }
}

// ---------------- launcher ---------------------------------------------------
extern "C" void kernel_launch(void* const* d_in, const int* in_sizes, int n_in,
                              void* d_out, int out_size) {
    const float* x     = (const float*)d_in[0];
    const float* W     = (const float*)d_in[1];
    const float* gamma = (const float*)d_in[2];
    const float* beta  = (const float*)d_in[3];
    float* out = (float*)d_out;

    zero_sums<<<1, 64>>>();
    sq_kernel<<<BB*NN/256, 256>>>(x);
    proj_kernel<<<BB*NN/4, 256>>>(x, W);
    knn_part_kernel<<<BB*(NN/QPB)*SPLIT, THR>>>(x);
    knn_merge_kernel<<<BB*NN/TQM, TQM>>>(x);
    sums_kernel<<<BB*NN/128, 256>>>();
    finalize_kernel<<<1, 64>>>(gamma, beta);
    out_kernel<<<BB*OO, 256>>>(out);
}

// round 12
// speedup vs baseline: 2.4507x; 2.4507x over previous
#include <cuda_runtime.h>
#include <math_constants.h>
#include <cstdint>

#define BB 8
#define NN 4096
#define DD 16
#define OO 64
#define KK 20
#define KP 24            // per-split fast-pass pad
#define SPLIT 4          // candidate splits per query
#define QTR (NN/SPLIT)   // 1024 candidates per split
#define CNT (8LL*4096*20)

#define TQ 64            // threads per knn block (1 thread = 1 query)
#define TC 128           // candidate tile rows
#define WARM 64          // candidates before first threshold compact
#define BUFCAP 512       // per-query pending buffer (local mem)

// ---------------- scratch (static device globals: no allocation) ------------
__device__ float  g_u[BB*NN*OO];
__device__ float  g_v[BB*NN*OO];
__device__ int    g_idx[BB*NN*KK];          // final knn indices
__device__ int    g_pidx[BB*NN*SPLIT*KP];   // per-split fast top-24 indices
__device__ float  g_sqf[BB*NN];             // XLA-emulated fp32 sum(x*x)
__device__ double g_sum[OO];
__device__ double g_sumsq[OO];
__device__ float  g_a[OO];
__device__ float  g_c[OO];

// ---------------- kernel 0: zero accumulators --------------------------------
__global__ void zero_sums() {
    int t = threadIdx.x;
    if (t < OO) { g_sum[t] = 0.0; g_sumsq[t] = 0.0; }
}

// ---------------- kernel 0b: XLA-emulated per-point squared norms -----------
// DO NOT CHANGE (bit-exact emulation of reference rounding; validated R3).
__global__ void sq_kernel(const float* __restrict__ x) {
    int p = blockIdx.x * blockDim.x + threadIdx.x;
    const float4* xp = (const float4*)(x + (size_t)p * DD);
    float s[4];
#pragma unroll
    for (int i = 0; i < 4; i++) {
        float4 v = xp[i];
        float a = __fmul_rn(v.x, v.x);
        a = __fadd_rn(a, __fmul_rn(v.y, v.y));
        a = __fadd_rn(a, __fmul_rn(v.z, v.z));
        a = __fadd_rn(a, __fmul_rn(v.w, v.w));
        s[i] = a;
    }
    g_sqf[p] = __fadd_rn(__fadd_rn(s[0], s[2]), __fadd_rn(s[1], s[3]));
}

// ---------------- kernel 1: per-point projections u, v ----------------------
__global__ void proj_kernel(const float* __restrict__ x,
                            const float* __restrict__ W) {
    __shared__ float Wt[2*DD][OO];
    __shared__ float xr[4][DD];
    int tid = threadIdx.x;
    for (int i = tid; i < OO*2*DD; i += blockDim.x) {
        int o = i / (2*DD), c = i % (2*DD);
        Wt[c][o] = W[i];
    }
    int p0 = blockIdx.x * 4;
    if (tid < 4*DD) xr[tid >> 4][tid & 15] = x[p0*DD + tid];
    __syncthreads();
    int o  = tid & 63;
    int nl = tid >> 6;
    float cacc = 0.f, facc = 0.f;
#pragma unroll
    for (int d = 0; d < DD; d++) {
        float xv = xr[nl][d];
        cacc = fmaf(Wt[d][o],      xv, cacc);
        facc = fmaf(Wt[DD + d][o], xv, facc);
    }
    int p = p0 + nl;
    g_u[p*OO + o] = cacc - facc;
    g_v[p*OO + o] = facc;
}

// ---------------- kNN helpers ------------------------------------------------
__device__ __forceinline__ float dot4(float4 a, float4 b) {
    return fmaf(a.x, b.x, fmaf(a.y, b.y, fmaf(a.z, b.z, a.w * b.w)));
}

__device__ __forceinline__ unsigned long long pack_key(float d, int gidx) {
    unsigned s = __float_as_uint(d);
    s ^= ((unsigned)((int)s >> 31)) | 0x80000000u;   // monotone f32->u32
    return ((unsigned long long)s << 32) | (unsigned)gidx;
}

__device__ __forceinline__ float unpack_d(unsigned long long key) {
    unsigned s = (unsigned)(key >> 32);
    s = (s & 0x80000000u) ? (s ^ 0x80000000u) : ~s;
    return __uint_as_float(s);
}

// drain pending local buffer into this thread's smem-resident sorted top-24
// column (hcol[j*TQ] = j-th best key). Rare path. u64 key compare keeps exact
// (d asc, idx asc) order == jax top_k tie-breaking.
__device__ __forceinline__ void compact(unsigned long long* __restrict__ buf,
                                        int& cnt,
                                        unsigned long long* __restrict__ hcol,
                                        float& thr) {
    unsigned long long worst = hcol[(KP-1)*TQ];
    for (int i = 0; i < cnt; i++) {
        unsigned long long key = buf[i];
        if (key < worst) {
            int j = KP - 1;
            while (j > 0) {
                unsigned long long cur = hcol[(j-1)*TQ];
                if (key < cur) { hcol[j*TQ] = cur; j--; }
                else break;
            }
            hcol[j*TQ] = key;
            worst = hcol[(KP-1)*TQ];
        }
    }
    cnt = 0;
    thr = unpack_d(worst);
}

// ---------------- kernel 2a: fast-pass kNN (946us hot loop, relaxed limits) -
// 1 thread = 1 query; score d' = sq_c - 2*q.c = d2 - sq_q (rank-equivalent
// per query). grid = BB * (NN/TQ) * SPLIT = 2048 blocks of 64 threads.

#define KNN_BODY(MLO, MHI)                                                    \
    _Pragma("unroll 4")                                                       \
    for (int m = (MLO); m < (MHI); m++) {                                     \
        float4 c0 = xs[m*4+0], c1 = xs[m*4+1], c2 = xs[m*4+2], c3 = xs[m*4+3];\
        float d  = (dot4(q0,c0) + dot4(q1,c1)) + (dot4(q2,c2) + dot4(q3,c3)); \
        float dp = fmaf(-2.f, d, sqs[m]);                                     \
        if (dp < thr) buf[cnt++] = pack_key(dp, cbase + t0 + m);              \
    }

__global__ __launch_bounds__(TQ, 9) void knn_part_kernel(const float* __restrict__ x) {
    __shared__ float4 xs[TC*4];                  // 8KB
    __shared__ float  sqs[TC];                   // 0.5KB
    __shared__ unsigned long long heap[KP*TQ];   // 12KB, [j][thread]

    int tid   = threadIdx.x;
    int b     = blockIdx.x >> 8;
    int rem   = blockIdx.x & 255;
    int qg    = rem >> 2;
    int split = rem & (SPLIT-1);
    int qn    = qg * TQ + tid;
    int cbase = split * QTR;

    const float* xb  = x + (size_t)b * NN * DD;
    const float* sqb = g_sqf + (size_t)b * NN;

    const float4* qp = (const float4*)(xb + (size_t)qn * DD);
    float4 q0 = qp[0], q1 = qp[1], q2 = qp[2], q3 = qp[3];

#pragma unroll
    for (int j = 0; j < KP; j++) heap[j*TQ + tid] = 0xFFFFFFFFFFFFFFFFull;
    unsigned long long* hcol = heap + tid;

    unsigned long long buf[BUFCAP];   // local memory pending buffer
    int cnt = 0;
    float thr = CUDART_INF_F;

    for (int t0 = 0; t0 < QTR; t0 += TC) {
        // cooperative stage: 2 rows per thread
#pragma unroll
        for (int i = 0; i < TC/TQ; i++) {
            int r = tid + i * TQ;
            const float4* src = (const float4*)(xb + (size_t)(cbase + t0 + r) * DD);
            xs[r*4 + 0] = src[0]; xs[r*4 + 1] = src[1];
            xs[r*4 + 2] = src[2]; xs[r*4 + 3] = src[3];
            sqs[r] = sqb[cbase + t0 + r];
        }
        __syncthreads();

        if (t0 == 0) {
            KNN_BODY(0, WARM)
            compact(buf, cnt, hcol, thr);     // finite threshold after 64
            KNN_BODY(WARM, TC)
        } else {
            KNN_BODY(0, TC)
        }
        __syncthreads();

        if (cnt >= BUFCAP - TC) compact(buf, cnt, hcol, thr);
    }
    compact(buf, cnt, hcol, thr);

    int* outp = g_pidx + (((size_t)b * NN + qn) * SPLIT + split) * KP;
#pragma unroll
    for (int j = 0; j < KP; j++) outp[j] = (int)(hcol[j*TQ] & 0xFFFFFFFFu);
}

// ---------------- kernel 2b: merge splits + emulated-reference refinement ---
// FROZEN numerics (validated R3): serial-FFMA dot k ascending;
// d2 = fl( fl(sqn + sqc) - fl(2*dot) ); u64 key = (monotone d2, idx).
#define TQM 64
__global__ __launch_bounds__(TQM) void knn_merge_kernel(const float* __restrict__ x) {
    int tid = threadIdx.x;
    int b   = blockIdx.x >> 6;
    int qn  = ((blockIdx.x & 63) << 6) + tid;
    const float* xb  = x + (size_t)b * NN * DD;
    const float* sqb = g_sqf + (size_t)b * NN;

    const float4* qp = (const float4*)(xb + (size_t)qn * DD);
    float4 q0 = qp[0], q1 = qp[1], q2 = qp[2], q3 = qp[3];
    float sqn = sqb[qn];

    unsigned long long outk[KK];
#pragma unroll
    for (int j = 0; j < KK; j++) outk[j] = 0xFFFFFFFFFFFFFFFFull;

    const int* pin = g_pidx + ((size_t)b * NN + qn) * SPLIT * KP;
#pragma unroll 4
    for (int j = 0; j < SPLIT * KP; j++) {
        int ci = pin[j];
        const float4* cp = (const float4*)(xb + (size_t)ci * DD);
        float4 c0 = cp[0], c1 = cp[1], c2 = cp[2], c3 = cp[3];
        float acc = 0.f;
        acc = fmaf(q0.x, c0.x, acc); acc = fmaf(q0.y, c0.y, acc);
        acc = fmaf(q0.z, c0.z, acc); acc = fmaf(q0.w, c0.w, acc);
        acc = fmaf(q1.x, c1.x, acc); acc = fmaf(q1.y, c1.y, acc);
        acc = fmaf(q1.z, c1.z, acc); acc = fmaf(q1.w, c1.w, acc);
        acc = fmaf(q2.x, c2.x, acc); acc = fmaf(q2.y, c2.y, acc);
        acc = fmaf(q2.z, c2.z, acc); acc = fmaf(q2.w, c2.w, acc);
        acc = fmaf(q3.x, c3.x, acc); acc = fmaf(q3.y, c3.y, acc);
        acc = fmaf(q3.z, c3.z, acc); acc = fmaf(q3.w, c3.w, acc);
        float ssum = __fadd_rn(sqn, sqb[ci]);
        float d2   = __fsub_rn(ssum, __fmul_rn(2.0f, acc));
        unsigned long long key = pack_key(d2, ci);
        if (key < outk[KK-1]) {
            outk[KK-1] = key;
#pragma unroll
            for (int t = KK-1; t > 0; --t) {
                if (outk[t] < outk[t-1]) {
                    unsigned long long tmp = outk[t];
                    outk[t] = outk[t-1]; outk[t-1] = tmp;
                } else break;
            }
        }
    }

    int* outp = g_idx + ((size_t)b * NN + qn) * KK;
#pragma unroll
    for (int j = 0; j < KK; j++) outp[j] = (int)(outk[j] & 0xFFFFFFFFu);
}

// ---------------- kernel 3: per-channel sum / sumsq over (b,n,k) ------------
__global__ void sums_kernel() {
    int tid = threadIdx.x;
    int o = tid & 63;
    int g = tid >> 6;
    float s = 0.f, s2 = 0.f;
    int r0 = (blockIdx.x * 4 + g) * 32;
    for (int i = 0; i < 32; i++) {
        int r = r0 + i;
        int b = r >> 12;
        float u = g_u[(size_t)r * OO + o];
        const int* ip = g_idx + (size_t)r * KK;
#pragma unroll
        for (int k = 0; k < KK; k++) {
            int gi = ip[k];
            float h = u + g_v[(((size_t)b << 12) + gi) * OO + o];
            s += h;
            s2 = fmaf(h, h, s2);
        }
    }
    atomicAdd(&g_sum[o],   (double)s);
    atomicAdd(&g_sumsq[o], (double)s2);
}

// ---------------- kernel 4: finalize affine coefficients --------------------
__global__ void finalize_kernel(const float* __restrict__ gamma,
                                const float* __restrict__ beta) {
    int o = threadIdx.x;
    if (o < OO) {
        double mean = g_sum[o] / (double)CNT;
        double var  = g_sumsq[o] / (double)CNT - mean * mean;
        double rstd = 1.0 / sqrt(var + 1e-5);
        float a = gamma[o] * (float)rstd;
        g_a[o] = a;
        g_c[o] = fmaf(-(float)mean, a, beta[o]);
    }
}

// ---------------- kernel 5: write output (coalesced, smem-staged) -----------
__global__ void out_kernel(float* __restrict__ out) {
    __shared__ float su[NN];
    __shared__ float sv[NN];
    int b = blockIdx.x >> 6;
    int o = blockIdx.x & 63;
    float a = g_a[o], c = g_c[o];
    int tid = threadIdx.x;
    size_t base = (size_t)b * NN * OO;
    for (int i = tid; i < NN; i += blockDim.x) {
        su[i] = fmaf(a, g_u[base + (size_t)i * OO + o], c);
        sv[i] = a * g_v[base + (size_t)i * OO + o];
    }
    __syncthreads();
    const int* ip = g_idx + (size_t)b * NN * KK;
    float* op = out + (size_t)blockIdx.x * (NN * KK);
    for (int e = tid; e < NN * KK; e += blockDim.x) {
        int n = e / KK;
        int gi = ip[e];
        float y = su[n] + sv[gi];
        op[e] = fmaxf(y, 0.f);
    }
}

// ---------------- launcher ---------------------------------------------------
extern "C" void kernel_launch(void* const* d_in, const int* in_sizes, int n_in,
                              void* d_out, int out_size) {
    const float* x     = (const float*)d_in[0];
    const float* W     = (const float*)d_in[1];
    const float* gamma = (const float*)d_in[2];
    const float* beta  = (const float*)d_in[3];
    float* out = (float*)d_out;

    zero_sums<<<1, 64>>>();
    sq_kernel<<<BB*NN/256, 256>>>(x);
    proj_kernel<<<BB*NN/4, 256>>>(x, W);
    knn_part_kernel<<<BB*(NN/TQ)*SPLIT, TQ>>>(x);
    knn_merge_kernel<<<BB*NN/TQM, TQM>>>(x);
    sums_kernel<<<BB*NN/128, 256>>>();
    finalize_kernel<<<1, 64>>>(gamma, beta);
    out_kernel<<<BB*OO, 256>>>(out);
}

// round 13
// speedup vs baseline: 3.2260x; 1.3164x over previous
#include <cuda_runtime.h>
#include <math_constants.h>
#include <cstdint>

#define BB 8
#define NN 4096
#define DD 16
#define OO 64
#define KK 20
#define KP 24            // per-split fast-pass pad
#define SPLIT 4          // candidate splits per query
#define QTR (NN/SPLIT)   // 1024 candidates per split
#define CNT (8LL*4096*20)

#define TQ 64            // threads per knn block (1 thread = 1 query)
#define TC 128           // candidate tile rows
#define WARM 64          // candidates before first threshold compact
#define BUFCAP 512       // per-query pending buffer (local mem)

// ---------------- scratch (static device globals: no allocation) ------------
__device__ float  g_u[BB*NN*OO];
__device__ float  g_v[BB*NN*OO];
__device__ int    g_idx[BB*NN*KK];          // final knn indices
__device__ int    g_pidx[BB*NN*SPLIT*KP];   // per-split fast top-24 indices
__device__ float  g_sqf[BB*NN];             // XLA-emulated fp32 sum(x*x)
__device__ double g_sum[OO];
__device__ double g_sumsq[OO];
__device__ float  g_a[OO];
__device__ float  g_c[OO];

// ---------------- kernel 0: zero accumulators --------------------------------
__global__ void zero_sums() {
    int t = threadIdx.x;
    if (t < OO) { g_sum[t] = 0.0; g_sumsq[t] = 0.0; }
}

// ---------------- kernel 0b: XLA-emulated per-point squared norms -----------
// DO NOT CHANGE (bit-exact emulation of reference rounding; validated R3).
__global__ void sq_kernel(const float* __restrict__ x) {
    int p = blockIdx.x * blockDim.x + threadIdx.x;
    const float4* xp = (const float4*)(x + (size_t)p * DD);
    float s[4];
#pragma unroll
    for (int i = 0; i < 4; i++) {
        float4 v = xp[i];
        float a = __fmul_rn(v.x, v.x);
        a = __fadd_rn(a, __fmul_rn(v.y, v.y));
        a = __fadd_rn(a, __fmul_rn(v.z, v.z));
        a = __fadd_rn(a, __fmul_rn(v.w, v.w));
        s[i] = a;
    }
    g_sqf[p] = __fadd_rn(__fadd_rn(s[0], s[2]), __fadd_rn(s[1], s[3]));
}

// ---------------- kernel 1: per-point projections u, v ----------------------
__global__ void proj_kernel(const float* __restrict__ x,
                            const float* __restrict__ W) {
    __shared__ float Wt[2*DD][OO];
    __shared__ float xr[4][DD];
    int tid = threadIdx.x;
    for (int i = tid; i < OO*2*DD; i += blockDim.x) {
        int o = i / (2*DD), c = i % (2*DD);
        Wt[c][o] = W[i];
    }
    int p0 = blockIdx.x * 4;
    if (tid < 4*DD) xr[tid >> 4][tid & 15] = x[p0*DD + tid];
    __syncthreads();
    int o  = tid & 63;
    int nl = tid >> 6;
    float cacc = 0.f, facc = 0.f;
#pragma unroll
    for (int d = 0; d < DD; d++) {
        float xv = xr[nl][d];
        cacc = fmaf(Wt[d][o],      xv, cacc);
        facc = fmaf(Wt[DD + d][o], xv, facc);
    }
    int p = p0 + nl;
    g_u[p*OO + o] = cacc - facc;
    g_v[p*OO + o] = facc;
}

// ---------------- kNN helpers ------------------------------------------------
__device__ __forceinline__ float dot4(float4 a, float4 b) {
    return fmaf(a.x, b.x, fmaf(a.y, b.y, fmaf(a.z, b.z, a.w * b.w)));
}

__device__ __forceinline__ unsigned long long pack_key(float d, int gidx) {
    unsigned s = __float_as_uint(d);
    s ^= ((unsigned)((int)s >> 31)) | 0x80000000u;   // monotone f32->u32
    return ((unsigned long long)s << 32) | (unsigned)gidx;
}

__device__ __forceinline__ float unpack_d(unsigned long long key) {
    unsigned s = (unsigned)(key >> 32);
    s = (s & 0x80000000u) ? (s ^ 0x80000000u) : ~s;
    return __uint_as_float(s);
}

// drain pending local buffer into this thread's smem-resident sorted top-24
// column (hcol[j*TQ] = j-th best key). Rare path. u64 key compare keeps exact
// (d asc, idx asc) order == jax top_k tie-breaking.
__device__ __forceinline__ void compact(unsigned long long* __restrict__ buf,
                                        int& cnt,
                                        unsigned long long* __restrict__ hcol,
                                        float& thr) {
    unsigned long long worst = hcol[(KP-1)*TQ];
    for (int i = 0; i < cnt; i++) {
        unsigned long long key = buf[i];
        if (key < worst) {
            int j = KP - 1;
            while (j > 0) {
                unsigned long long cur = hcol[(j-1)*TQ];
                if (key < cur) { hcol[j*TQ] = cur; j--; }
                else break;
            }
            hcol[j*TQ] = key;
            worst = hcol[(KP-1)*TQ];
        }
    }
    cnt = 0;
    thr = unpack_d(worst);
}

// ---------------- kernel 2a: fast-pass kNN (R4 hot loop verbatim) -----------
// 1 thread = 1 query over QTR candidates; R4 epilogue with sqn restored.
// grid = BB * (NN/TQ) * SPLIT = 2048 blocks of 64 threads.

#define KNN_BODY(MLO, MHI)                                                    \
    _Pragma("unroll 4")                                                       \
    for (int m = (MLO); m < (MHI); m++) {                                     \
        float4 c0 = xs[m*4+0], c1 = xs[m*4+1], c2 = xs[m*4+2], c3 = xs[m*4+3];\
        float d  = (dot4(q0,c0) + dot4(q1,c1)) + (dot4(q2,c2) + dot4(q3,c3)); \
        float d2 = fmaf(-2.f, d, sqn + sqs[m]);                               \
        if (d2 < thr) buf[cnt++] = pack_key(d2, cbase + t0 + m);              \
    }

__global__ __launch_bounds__(TQ, 8) void knn_part_kernel(const float* __restrict__ x) {
    __shared__ float4 xs[TC*4];                  // 8KB
    __shared__ float  sqs[TC];                   // 0.5KB
    __shared__ unsigned long long heap[KP*TQ];   // 12KB, [j][thread]

    int tid   = threadIdx.x;
    int b     = blockIdx.x >> 8;
    int rem   = blockIdx.x & 255;
    int qg    = rem >> 2;
    int split = rem & (SPLIT-1);
    int qn    = qg * TQ + tid;
    int cbase = split * QTR;

    const float* xb  = x + (size_t)b * NN * DD;
    const float* sqb = g_sqf + (size_t)b * NN;

    const float4* qp = (const float4*)(xb + (size_t)qn * DD);
    float4 q0 = qp[0], q1 = qp[1], q2 = qp[2], q3 = qp[3];
    float sqn = sqb[qn];

#pragma unroll
    for (int j = 0; j < KP; j++) heap[j*TQ + tid] = 0xFFFFFFFFFFFFFFFFull;
    unsigned long long* hcol = heap + tid;

    unsigned long long buf[BUFCAP];   // local memory pending buffer
    int cnt = 0;
    float thr = CUDART_INF_F;

    for (int t0 = 0; t0 < QTR; t0 += TC) {
        // cooperative stage: 2 rows per thread
#pragma unroll
        for (int i = 0; i < TC/TQ; i++) {
            int r = tid + i * TQ;
            const float4* src = (const float4*)(xb + (size_t)(cbase + t0 + r) * DD);
            xs[r*4 + 0] = src[0]; xs[r*4 + 1] = src[1];
            xs[r*4 + 2] = src[2]; xs[r*4 + 3] = src[3];
            sqs[r] = sqb[cbase + t0 + r];
        }
        __syncthreads();

        if (t0 == 0) {
            KNN_BODY(0, WARM)
            compact(buf, cnt, hcol, thr);     // finite threshold after 64
            KNN_BODY(WARM, TC)
        } else {
            KNN_BODY(0, TC)
        }
        __syncthreads();

        // warp-uniform overflow trigger (R4 style)
        if (__any_sync(0xffffffffu, cnt >= BUFCAP - TC))
            compact(buf, cnt, hcol, thr);
    }
    compact(buf, cnt, hcol, thr);

    int* outp = g_pidx + (((size_t)b * NN + qn) * SPLIT + split) * KP;
#pragma unroll
    for (int j = 0; j < KP; j++) outp[j] = (int)(hcol[j*TQ] & 0xFFFFFFFFu);
}

// ---------------- kernel 2b: merge splits + emulated-reference refinement ---
// FROZEN numerics (validated R3): serial-FFMA dot k ascending;
// d2 = fl( fl(sqn + sqc) - fl(2*dot) ); u64 key = (monotone d2, idx).
#define TQM 64
__global__ __launch_bounds__(TQM) void knn_merge_kernel(const float* __restrict__ x) {
    int tid = threadIdx.x;
    int b   = blockIdx.x >> 6;
    int qn  = ((blockIdx.x & 63) << 6) + tid;
    const float* xb  = x + (size_t)b * NN * DD;
    const float* sqb = g_sqf + (size_t)b * NN;

    const float4* qp = (const float4*)(xb + (size_t)qn * DD);
    float4 q0 = qp[0], q1 = qp[1], q2 = qp[2], q3 = qp[3];
    float sqn = sqb[qn];

    unsigned long long outk[KK];
#pragma unroll
    for (int j = 0; j < KK; j++) outk[j] = 0xFFFFFFFFFFFFFFFFull;

    const int* pin = g_pidx + ((size_t)b * NN + qn) * SPLIT * KP;
#pragma unroll 4
    for (int j = 0; j < SPLIT * KP; j++) {
        int ci = pin[j];
        const float4* cp = (const float4*)(xb + (size_t)ci * DD);
        float4 c0 = cp[0], c1 = cp[1], c2 = cp[2], c3 = cp[3];
        float acc = 0.f;
        acc = fmaf(q0.x, c0.x, acc); acc = fmaf(q0.y, c0.y, acc);
        acc = fmaf(q0.z, c0.z, acc); acc = fmaf(q0.w, c0.w, acc);
        acc = fmaf(q1.x, c1.x, acc); acc = fmaf(q1.y, c1.y, acc);
        acc = fmaf(q1.z, c1.z, acc); acc = fmaf(q1.w, c1.w, acc);
        acc = fmaf(q2.x, c2.x, acc); acc = fmaf(q2.y, c2.y, acc);
        acc = fmaf(q2.z, c2.z, acc); acc = fmaf(q2.w, c2.w, acc);
        acc = fmaf(q3.x, c3.x, acc); acc = fmaf(q3.y, c3.y, acc);
        acc = fmaf(q3.z, c3.z, acc); acc = fmaf(q3.w, c3.w, acc);
        float ssum = __fadd_rn(sqn, sqb[ci]);
        float d2   = __fsub_rn(ssum, __fmul_rn(2.0f, acc));
        unsigned long long key = pack_key(d2, ci);
        if (key < outk[KK-1]) {
            outk[KK-1] = key;
#pragma unroll
            for (int t = KK-1; t > 0; --t) {
                if (outk[t] < outk[t-1]) {
                    unsigned long long tmp = outk[t];
                    outk[t] = outk[t-1]; outk[t-1] = tmp;
                } else break;
            }
        }
    }

    int* outp = g_idx + ((size_t)b * NN + qn) * KK;
#pragma unroll
    for (int j = 0; j < KK; j++) outp[j] = (int)(outk[j] & 0xFFFFFFFFu);
}

// ---------------- kernel 3: per-channel sum / sumsq over (b,n,k) ------------
__global__ void sums_kernel() {
    int tid = threadIdx.x;
    int o = tid & 63;
    int g = tid >> 6;
    float s = 0.f, s2 = 0.f;
    int r0 = (blockIdx.x * 4 + g) * 32;
    for (int i = 0; i < 32; i++) {
        int r = r0 + i;
        int b = r >> 12;
        float u = g_u[(size_t)r * OO + o];
        const int* ip = g_idx + (size_t)r * KK;
#pragma unroll
        for (int k = 0; k < KK; k++) {
            int gi = ip[k];
            float h = u + g_v[(((size_t)b << 12) + gi) * OO + o];
            s += h;
            s2 = fmaf(h, h, s2);
        }
    }
    atomicAdd(&g_sum[o],   (double)s);
    atomicAdd(&g_sumsq[o], (double)s2);
}

// ---------------- kernel 4: finalize affine coefficients --------------------
__global__ void finalize_kernel(const float* __restrict__ gamma,
                                const float* __restrict__ beta) {
    int o = threadIdx.x;
    if (o < OO) {
        double mean = g_sum[o] / (double)CNT;
        double var  = g_sumsq[o] / (double)CNT - mean * mean;
        double rstd = 1.0 / sqrt(var + 1e-5);
        float a = gamma[o] * (float)rstd;
        g_a[o] = a;
        g_c[o] = fmaf(-(float)mean, a, beta[o]);
    }
}

// ---------------- kernel 5: write output (coalesced, smem-staged) -----------
__global__ void out_kernel(float* __restrict__ out) {
    __shared__ float su[NN];
    __shared__ float sv[NN];
    int b = blockIdx.x >> 6;
    int o = blockIdx.x & 63;
    float a = g_a[o], c = g_c[o];
    int tid = threadIdx.x;
    size_t base = (size_t)b * NN * OO;
    for (int i = tid; i < NN; i += blockDim.x) {
        su[i] = fmaf(a, g_u[base + (size_t)i * OO + o], c);
        sv[i] = a * g_v[base + (size_t)i * OO + o];
    }
    __syncthreads();
    const int* ip = g_idx + (size_t)b * NN * KK;
    float* op = out + (size_t)blockIdx.x * (NN * KK);
    for (int e = tid; e < NN * KK; e += blockDim.x) {
        int n = e / KK;
        int gi = ip[e];
        float y = su[n] + sv[gi];
        op[e] = fmaxf(y, 0.f);
    }
}

// ---------------- launcher ---------------------------------------------------
extern "C" void kernel_launch(void* const* d_in, const int* in_sizes, int n_in,
                              void* d_out, int out_size) {
    const float* x     = (const float*)d_in[0];
    const float* W     = (const float*)d_in[1];
    const float* gamma = (const float*)d_in[2];
    const float* beta  = (const float*)d_in[3];
    float* out = (float*)d_out;

    zero_sums<<<1, 64>>>();
    sq_kernel<<<BB*NN/256, 256>>>(x);
    proj_kernel<<<BB*NN/4, 256>>>(x, W);
    knn_part_kernel<<<BB*(NN/TQ)*SPLIT, TQ>>>(x);
    knn_merge_kernel<<<BB*NN/TQM, TQM>>>(x);
    sums_kernel<<<BB*NN/128, 256>>>();
    finalize_kernel<<<1, 64>>>(gamma, beta);
    out_kernel<<<BB*OO, 256>>>(out);
}

// round 14
// speedup vs baseline: 5.0854x; 1.5764x over previous
#include <cuda_runtime.h>
#include <math_constants.h>
#include <cstdint>

#define BB 8
#define NN 4096
#define DD 16
#define OO 64
#define KK 20
#define KP 24            // per-split fast-pass pad
#define SPLIT 4          // candidate splits per query
#define QTR (NN/SPLIT)   // 1024 candidates per split
#define CNT (8LL*4096*20)

#define TQ 64            // threads per knn block (1 thread = 1 query)
#define TC 128           // candidate tile rows
#define BUFCAP 512       // per-query pending buffer (local mem)

// ---------------- scratch (static device globals: no allocation) ------------
__device__ float  g_u[BB*NN*OO];
__device__ float  g_v[BB*NN*OO];
__device__ int    g_idx[BB*NN*KK];          // final knn indices
__device__ int    g_pidx[BB*NN*SPLIT*KP];   // per-split fast top-24 indices
__device__ float  g_sqf[BB*NN];             // XLA-emulated fp32 sum(x*x)
__device__ double g_sum[OO];
__device__ double g_sumsq[OO];
__device__ float  g_a[OO];
__device__ float  g_c[OO];

// ---------------- kernel 0: zero accumulators --------------------------------
__global__ void zero_sums() {
    int t = threadIdx.x;
    if (t < OO) { g_sum[t] = 0.0; g_sumsq[t] = 0.0; }
}

// ---------------- kernel 0b: XLA-emulated per-point squared norms -----------
// DO NOT CHANGE (bit-exact emulation of reference rounding; validated R3).
__global__ void sq_kernel(const float* __restrict__ x) {
    int p = blockIdx.x * blockDim.x + threadIdx.x;
    const float4* xp = (const float4*)(x + (size_t)p * DD);
    float s[4];
#pragma unroll
    for (int i = 0; i < 4; i++) {
        float4 v = xp[i];
        float a = __fmul_rn(v.x, v.x);
        a = __fadd_rn(a, __fmul_rn(v.y, v.y));
        a = __fadd_rn(a, __fmul_rn(v.z, v.z));
        a = __fadd_rn(a, __fmul_rn(v.w, v.w));
        s[i] = a;
    }
    g_sqf[p] = __fadd_rn(__fadd_rn(s[0], s[2]), __fadd_rn(s[1], s[3]));
}

// ---------------- kernel 1: per-point projections u, v ----------------------
__global__ void proj_kernel(const float* __restrict__ x,
                            const float* __restrict__ W) {
    __shared__ float Wt[2*DD][OO];
    __shared__ float xr[4][DD];
    int tid = threadIdx.x;
    for (int i = tid; i < OO*2*DD; i += blockDim.x) {
        int o = i / (2*DD), c = i % (2*DD);
        Wt[c][o] = W[i];
    }
    int p0 = blockIdx.x * 4;
    if (tid < 4*DD) xr[tid >> 4][tid & 15] = x[p0*DD + tid];
    __syncthreads();
    int o  = tid & 63;
    int nl = tid >> 6;
    float cacc = 0.f, facc = 0.f;
#pragma unroll
    for (int d = 0; d < DD; d++) {
        float xv = xr[nl][d];
        cacc = fmaf(Wt[d][o],      xv, cacc);
        facc = fmaf(Wt[DD + d][o], xv, facc);
    }
    int p = p0 + nl;
    g_u[p*OO + o] = cacc - facc;
    g_v[p*OO + o] = facc;
}

// ---------------- kNN helpers ------------------------------------------------
__device__ __forceinline__ float dot4(float4 a, float4 b) {
    return fmaf(a.x, b.x, fmaf(a.y, b.y, fmaf(a.z, b.z, a.w * b.w)));
}

__device__ __forceinline__ unsigned long long pack_key(float d, int gidx) {
    unsigned s = __float_as_uint(d);
    s ^= ((unsigned)((int)s >> 31)) | 0x80000000u;   // monotone f32->u32
    return ((unsigned long long)s << 32) | (unsigned)gidx;
}

__device__ __forceinline__ float unpack_d(unsigned long long key) {
    unsigned s = (unsigned)(key >> 32);
    s = (s & 0x80000000u) ? (s ^ 0x80000000u) : ~s;
    return __uint_as_float(s);
}

// drain pending local buffer into this thread's smem-resident sorted top-24
// column (hcol[j*TQ] = j-th best key). Rare path. u64 key compare keeps exact
// (d asc, idx asc) order == jax top_k tie-breaking.
__device__ __forceinline__ void compact(unsigned long long* __restrict__ buf,
                                        int& cnt,
                                        unsigned long long* __restrict__ hcol,
                                        float& thr) {
    unsigned long long worst = hcol[(KP-1)*TQ];
    for (int i = 0; i < cnt; i++) {
        unsigned long long key = buf[i];
        if (key < worst) {
            int j = KP - 1;
            while (j > 0) {
                unsigned long long cur = hcol[(j-1)*TQ];
                if (key < cur) { hcol[j*TQ] = cur; j--; }
                else break;
            }
            hcol[j*TQ] = key;
            worst = hcol[(KP-1)*TQ];
        }
    }
    cnt = 0;
    thr = unpack_d(worst);
}

// ---------------- kernel 2a: fast-pass kNN (R4 code shape, verbatim) --------
// 1 thread = 1 query over QTR candidates. ONE body instantiation, ONE in-loop
// compact site (need-boolean) — this shape compiles to 113 regs, no spill.
// grid = BB * (NN/TQ) * SPLIT = 2048 blocks of 64 threads.
__global__ __launch_bounds__(TQ, 8) void knn_part_kernel(const float* __restrict__ x) {
    __shared__ float4 xs[TC*4];                  // 8KB
    __shared__ float  sqs[TC];                   // 0.5KB
    __shared__ unsigned long long heap[KP*TQ];   // 12KB, [j][thread]

    int tid   = threadIdx.x;
    int b     = blockIdx.x >> 8;
    int rem   = blockIdx.x & 255;
    int qg    = rem >> 2;
    int split = rem & (SPLIT-1);
    int qn    = qg * TQ + tid;
    int cbase = split * QTR;

    const float* xb  = x + (size_t)b * NN * DD;
    const float* sqb = g_sqf + (size_t)b * NN;

    const float4* qp = (const float4*)(xb + (size_t)qn * DD);
    float4 q0 = qp[0], q1 = qp[1], q2 = qp[2], q3 = qp[3];
    float sqn = sqb[qn];

#pragma unroll
    for (int j = 0; j < KP; j++) heap[j*TQ + tid] = 0xFFFFFFFFFFFFFFFFull;
    unsigned long long* hcol = heap + tid;

    unsigned long long buf[BUFCAP];   // local memory pending buffer
    int cnt = 0;
    float thr = CUDART_INF_F;

    for (int t0 = 0; t0 < QTR; t0 += TC) {
        // cooperative stage: 2 rows per thread
#pragma unroll
        for (int i = 0; i < TC/TQ; i++) {
            int r = tid + i * TQ;
            const float4* src = (const float4*)(xb + (size_t)(cbase + t0 + r) * DD);
            xs[r*4 + 0] = src[0]; xs[r*4 + 1] = src[1];
            xs[r*4 + 2] = src[2]; xs[r*4 + 3] = src[3];
            sqs[r] = sqb[cbase + t0 + r];
        }
        __syncthreads();

#pragma unroll 4
        for (int m = 0; m < TC; m++) {
            float4 c0 = xs[m*4+0], c1 = xs[m*4+1], c2 = xs[m*4+2], c3 = xs[m*4+3];
            float d  = (dot4(q0,c0) + dot4(q1,c1)) + (dot4(q2,c2) + dot4(q3,c3));
            float d2 = fmaf(-2.f, d, sqn + sqs[m]);
            if (d2 < thr) {
                buf[cnt++] = pack_key(d2, cbase + t0 + m);
            }
        }
        __syncthreads();

        // establish threshold after first tile; afterwards only drain when the
        // buffer could overflow within the next tile (warp-uniform trigger).
        bool need = (t0 == 0) || __any_sync(0xffffffffu, cnt >= BUFCAP - TC);
        if (need) compact(buf, cnt, hcol, thr);
    }
    compact(buf, cnt, hcol, thr);

    int* outp = g_pidx + (((size_t)b * NN + qn) * SPLIT + split) * KP;
#pragma unroll
    for (int j = 0; j < KP; j++) outp[j] = (int)(hcol[j*TQ] & 0xFFFFFFFFu);
}

// ---------------- kernel 2b: merge splits + emulated-reference refinement ---
// FROZEN numerics (validated R3): serial-FFMA dot k ascending;
// d2 = fl( fl(sqn + sqc) - fl(2*dot) ); u64 key = (monotone d2, idx).
#define TQM 64
__global__ __launch_bounds__(TQM) void knn_merge_kernel(const float* __restrict__ x) {
    int tid = threadIdx.x;
    int b   = blockIdx.x >> 6;
    int qn  = ((blockIdx.x & 63) << 6) + tid;
    const float* xb  = x + (size_t)b * NN * DD;
    const float* sqb = g_sqf + (size_t)b * NN;

    const float4* qp = (const float4*)(xb + (size_t)qn * DD);
    float4 q0 = qp[0], q1 = qp[1], q2 = qp[2], q3 = qp[3];
    float sqn = sqb[qn];

    unsigned long long outk[KK];
#pragma unroll
    for (int j = 0; j < KK; j++) outk[j] = 0xFFFFFFFFFFFFFFFFull;

    const int* pin = g_pidx + ((size_t)b * NN + qn) * SPLIT * KP;
#pragma unroll 4
    for (int j = 0; j < SPLIT * KP; j++) {
        int ci = pin[j];
        const float4* cp = (const float4*)(xb + (size_t)ci * DD);
        float4 c0 = cp[0], c1 = cp[1], c2 = cp[2], c3 = cp[3];
        float acc = 0.f;
        acc = fmaf(q0.x, c0.x, acc); acc = fmaf(q0.y, c0.y, acc);
        acc = fmaf(q0.z, c0.z, acc); acc = fmaf(q0.w, c0.w, acc);
        acc = fmaf(q1.x, c1.x, acc); acc = fmaf(q1.y, c1.y, acc);
        acc = fmaf(q1.z, c1.z, acc); acc = fmaf(q1.w, c1.w, acc);
        acc = fmaf(q2.x, c2.x, acc); acc = fmaf(q2.y, c2.y, acc);
        acc = fmaf(q2.z, c2.z, acc); acc = fmaf(q2.w, c2.w, acc);
        acc = fmaf(q3.x, c3.x, acc); acc = fmaf(q3.y, c3.y, acc);
        acc = fmaf(q3.z, c3.z, acc); acc = fmaf(q3.w, c3.w, acc);
        float ssum = __fadd_rn(sqn, sqb[ci]);
        float d2   = __fsub_rn(ssum, __fmul_rn(2.0f, acc));
        unsigned long long key = pack_key(d2, ci);
        if (key < outk[KK-1]) {
            outk[KK-1] = key;
#pragma unroll
            for (int t = KK-1; t > 0; --t) {
                if (outk[t] < outk[t-1]) {
                    unsigned long long tmp = outk[t];
                    outk[t] = outk[t-1]; outk[t-1] = tmp;
                } else break;
            }
        }
    }

    int* outp = g_idx + ((size_t)b * NN + qn) * KK;
#pragma unroll
    for (int j = 0; j < KK; j++) outp[j] = (int)(outk[j] & 0xFFFFFFFFu);
}

// ---------------- kernel 3: per-channel sum / sumsq over (b,n,k) ------------
__global__ void sums_kernel() {
    int tid = threadIdx.x;
    int o = tid & 63;
    int g = tid >> 6;
    float s = 0.f, s2 = 0.f;
    int r0 = (blockIdx.x * 4 + g) * 32;
    for (int i = 0; i < 32; i++) {
        int r = r0 + i;
        int b = r >> 12;
        float u = g_u[(size_t)r * OO + o];
        const int* ip = g_idx + (size_t)r * KK;
#pragma unroll
        for (int k = 0; k < KK; k++) {
            int gi = ip[k];
            float h = u + g_v[(((size_t)b << 12) + gi) * OO + o];
            s += h;
            s2 = fmaf(h, h, s2);
        }
    }
    atomicAdd(&g_sum[o],   (double)s);
    atomicAdd(&g_sumsq[o], (double)s2);
}

// ---------------- kernel 4: finalize affine coefficients --------------------
__global__ void finalize_kernel(const float* __restrict__ gamma,
                                const float* __restrict__ beta) {
    int o = threadIdx.x;
    if (o < OO) {
        double mean = g_sum[o] / (double)CNT;
        double var  = g_sumsq[o] / (double)CNT - mean * mean;
        double rstd = 1.0 / sqrt(var + 1e-5);
        float a = gamma[o] * (float)rstd;
        g_a[o] = a;
        g_c[o] = fmaf(-(float)mean, a, beta[o]);
    }
}

// ---------------- kernel 5: write output (coalesced, smem-staged) -----------
__global__ void out_kernel(float* __restrict__ out) {
    __shared__ float su[NN];
    __shared__ float sv[NN];
    int b = blockIdx.x >> 6;
    int o = blockIdx.x & 63;
    float a = g_a[o], c = g_c[o];
    int tid = threadIdx.x;
    size_t base = (size_t)b * NN * OO;
    for (int i = tid; i < NN; i += blockDim.x) {
        su[i] = fmaf(a, g_u[base + (size_t)i * OO + o], c);
        sv[i] = a * g_v[base + (size_t)i * OO + o];
    }
    __syncthreads();
    const int* ip = g_idx + (size_t)b * NN * KK;
    float* op = out + (size_t)blockIdx.x * (NN * KK);
    for (int e = tid; e < NN * KK; e += blockDim.x) {
        int n = e / KK;
        int gi = ip[e];
        float y = su[n] + sv[gi];
        op[e] = fmaxf(y, 0.f);
    }
}

// ---------------- launcher ---------------------------------------------------
extern "C" void kernel_launch(void* const* d_in, const int* in_sizes, int n_in,
                              void* d_out, int out_size) {
    const float* x     = (const float*)d_in[0];
    const float* W     = (const float*)d_in[1];
    const float* gamma = (const float*)d_in[2];
    const float* beta  = (const float*)d_in[3];
    float* out = (float*)d_out;

    zero_sums<<<1, 64>>>();
    sq_kernel<<<BB*NN/256, 256>>>(x);
    proj_kernel<<<BB*NN/4, 256>>>(x, W);
    knn_part_kernel<<<BB*(NN/TQ)*SPLIT, TQ>>>(x);
    knn_merge_kernel<<<BB*NN/TQM, TQM>>>(x);
    sums_kernel<<<BB*NN/128, 256>>>();
    finalize_kernel<<<1, 64>>>(gamma, beta);
    out_kernel<<<BB*OO, 256>>>(out);
}